// round 15
// baseline (speedup 1.0000x reference)
#include <cuda_runtime.h>
#include <cuda_fp16.h>
#include <math.h>
#include <stdint.h>

#define BATCH 4096
#define T 25
#define CT 32
#define FIN 800
#define GO 64
#define H 256
#define VE 16
#define VR 12
#define KE 400
#define KR 300
#define KPE 448
#define KPR 320
#define NTHR 512
#define NTASK 104
#define B_ERR_OFS (256 * KPE)
#define B_TOT (256 * KPE + 256 * KPR)
#define SM_GEMM 87552     /* 64*912 + 32*912 (ecc worst case) */

// ---------------- device scratch ----------------
__device__ float g_U[4][T * GO];
__device__ float g_S[4][GO];
__device__ int   g_ctr;
__device__ __align__(16) __half g_Bf[B_TOT];   // [n][K_pad] fp16, ecc then err
__device__ float g_C[2][H];
__device__ __align__(16) float g_EG[BATCH * H];
__device__ __align__(16) float g_RG[BATCH * H];

// ---------------- helpers ----------------
__device__ __forceinline__ void mma16816(float* d, uint32_t a0, uint32_t a1,
                                         uint32_t a2, uint32_t a3,
                                         uint32_t b0, uint32_t b1) {
    asm volatile(
        "mma.sync.aligned.m16n8k16.row.col.f32.f16.f16.f32 "
        "{%0,%1,%2,%3}, {%4,%5,%6,%7}, {%8,%9}, {%0,%1,%2,%3};"
        : "+f"(d[0]), "+f"(d[1]), "+f"(d[2]), "+f"(d[3])
        : "r"(a0), "r"(a1), "r"(a2), "r"(a3), "r"(b0), "r"(b1));
}
__device__ __forceinline__ void ldsm4(uint32_t* r, uint32_t addr) {
    asm volatile(
        "ldmatrix.sync.aligned.m8n8.x4.shared.b16 {%0,%1,%2,%3}, [%4];"
        : "=r"(r[0]), "=r"(r[1]), "=r"(r[2]), "=r"(r[3])
        : "r"(addr));
}
__device__ __forceinline__ uint32_t pack_h2(__half lo, __half hi) {
    return ((uint32_t)__half_as_ushort(hi) << 16) |
           (uint32_t)__half_as_ushort(lo);
}
__device__ __forceinline__ uint32_t smem_u32(const void* p) {
    uint32_t a;
    asm("{ .reg .u64 t; cvta.to.shared.u64 t, %1; cvt.u32.u64 %0, t; }"
        : "=r"(a) : "l"(p));
    return a;
}

// ===== fused precompute: U/S tasks + spin-sync + B + C (R12-proven) =====
__global__ void __launch_bounds__(256) k_pre2(
    const float* __restrict__ Pe, const float* __restrict__ Pr,
    const float* __restrict__ pbe, const float* __restrict__ pbr,
    const float* __restrict__ chbe, const float* __restrict__ chbr,
    const float* __restrict__ cwe, const float* __restrict__ cbe,
    const float* __restrict__ cwr, const float* __restrict__ cbr,
    const float* __restrict__ Wche, const float* __restrict__ Wchr,
    const int* __restrict__ eie, int Ee, const int* __restrict__ eir, int Er) {
    __shared__ float sP[64 * 64];
    __shared__ float sQ[64 * 64];
    __shared__ float sU0[T * GO];
    __shared__ float sU1[T * GO];
    __shared__ float swe[64];
    __shared__ float sws[16];
    const int tid = threadIdx.x;
    const int b = blockIdx.x;
    const int o = tid & 63;
    const int cc = tid >> 6;
    float* red = sQ;

    if (b < 100) {
        const int mat = b / T, tp = b % T;
        const int branch = mat >> 1, which = mat & 1;
        const float* cw = branch ? cwr : cwe;
        const float* W = (branch ? Wchr : Wche) + which * FIN * GO;
        float acc = 0.f;
#pragma unroll
        for (int k = 0; k < 3; k++) {
            int t = tp - k + 1;
            if (t >= 0 && t < T) {
#pragma unroll
                for (int cj = 0; cj < 8; cj++) {
                    int c = cc * 8 + cj;
                    acc += cw[c * 3 + k] * W[(c * T + t) * GO + o];
                }
            }
        }
        red[tid] = acc;
        __syncthreads();
        if (tid < 64)
            g_U[mat][tp * GO + tid] =
                red[tid] + red[64 + tid] + red[128 + tid] + red[192 + tid];
        __syncthreads();
        __threadfence();
        if (tid == 0) atomicAdd(&g_ctr, 1);
    } else if (b < 104) {
        const int mat = b - 100;
        const int branch = mat >> 1, which = mat & 1;
        const float* cb = branch ? cbr : cbe;
        const float* W = (branch ? Wchr : Wche) + which * FIN * GO;
        float acc = 0.f;
#pragma unroll
        for (int cj = 0; cj < 8; cj++) {
            int c = cc * 8 + cj;
            float s = 0.f;
#pragma unroll
            for (int t = 0; t < T; t++) s += W[(c * T + t) * GO + o];
            acc += cb[c] * s;
        }
        red[tid] = acc;
        __syncthreads();
        if (tid < 64)
            g_S[mat][tid] =
                red[tid] + red[64 + tid] + red[128 + tid] + red[192 + tid];
        __syncthreads();
        __threadfence();
        if (tid == 0) atomicAdd(&g_ctr, 1);
    }

    if (b < (VE + VR) * 4) {
        const int vb = b >> 2, hb = (b & 3) * 64;
        const int br = vb >= VE;
        const int v = br ? vb - VE : vb;
        const float* P = br ? Pr : Pe;
        const int* ei = br ? eir : eie;
        const int E = br ? Er : Ee;
        const size_t base = br ? (size_t)B_ERR_OFS : 0;
        const int KP = br ? KPR : KPE;

        if (tid < E) {
            int s = ei[tid], d = ei[E + tid];
            int degs = 0, degd = 0;
            for (int i = 0; i < E; i++) {
                int si = ei[i];
                degs += (si == s);
                degd += (si == d);
            }
            float ds = degs > 0 ? rsqrtf((float)degs) : 0.f;
            float dd = degd > 0 ? rsqrtf((float)degd) : 0.f;
            swe[tid] = -ds * dd;
        }
        __syncthreads();
        int cnt = 0;
        int nd[4] = {0, 0, 0, 0};
        float nw[4] = {0.f, 0.f, 0.f, 0.f};
        for (int e = 0; e < E; e++) {
            if (ei[e] == v && cnt < 4) {
                nd[cnt] = ei[E + e];
                nw[cnt] = swe[e];
                cnt++;
            }
        }

        for (int i4 = tid; i4 < 1024; i4 += 256) {
            int oo = i4 >> 4, hl4 = (i4 & 15) * 4;
            ((float4*)sP)[i4] = *(const float4*)&P[(v * GO + oo) * H + hb + hl4];
            float4 q = make_float4(0.f, 0.f, 0.f, 0.f);
#pragma unroll
            for (int j = 0; j < 4; j++) {
                if (j < cnt) {
                    float4 pd = *(const float4*)&P[(nd[j] * GO + oo) * H + hb + hl4];
                    q.x += nw[j] * pd.x;
                    q.y += nw[j] * pd.y;
                    q.z += nw[j] * pd.z;
                    q.w += nw[j] * pd.w;
                }
            }
            ((float4*)sQ)[i4] = q;
        }

        if (tid == 0) {
            while (atomicAdd(&g_ctr, 0) < NTASK) {
            }
        }
        __syncthreads();
        __threadfence();
        {
            const float4* U0 = (const float4*)g_U[2 * br];
            const float4* U1 = (const float4*)g_U[2 * br + 1];
            for (int i = tid; i < T * GO / 4; i += 256) {
                ((float4*)sU0)[i] = U0[i];
                ((float4*)sU1)[i] = U1[i];
            }
        }
        __syncthreads();

        const int hl4 = (tid & 15) * 4;
        const int tpg = tid >> 4;
        for (int tp = tpg; tp < T; tp += 16) {
            float4 acc = make_float4(0.f, 0.f, 0.f, 0.f);
#pragma unroll 16
            for (int oo = 0; oo < 64; oo++) {
                float4 p = *(const float4*)&sP[oo * 64 + hl4];
                float4 q = *(const float4*)&sQ[oo * 64 + hl4];
                float u0 = sU0[tp * GO + oo];
                float u1 = sU1[tp * GO + oo];
                acc.x += u0 * p.x + u1 * q.x;
                acc.y += u0 * p.y + u1 * q.y;
                acc.z += u0 * p.z + u1 * q.z;
                acc.w += u0 * p.w + u1 * q.w;
            }
            const int kg = v * T + tp;
            float vals[4] = {acc.x, acc.y, acc.z, acc.w};
#pragma unroll
            for (int j = 0; j < 4; j++) {
                int n = hb + hl4 + j;
                g_Bf[base + (size_t)n * KP + kg] = __float2half_rn(vals[j]);
            }
        }
    } else if (b < (VE + VR) * 4 + 16) {
        const int cb = b - (VE + VR) * 4;
        const int br = cb >> 3;
        const int hc = cb & 7;
        const float* chb = br ? chbr : chbe;
        const float* pb = br ? pbr : pbe;
        const float* P = br ? Pr : Pe;
        const int* ei = br ? eir : eie;
        const int E = br ? Er : Ee;
        const int V = br ? VR : VE;
        float* cfo = sP;
        float* s1v = sP + 64;
        float* red2 = sP + 160;

        if (tid < E) {
            int s = ei[tid], d = ei[E + tid];
            int degs = 0, degd = 0;
            for (int i = 0; i < E; i++) {
                int si = ei[i];
                degs += (si == s);
                degd += (si == d);
            }
            float ds = degs > 0 ? rsqrtf((float)degs) : 0.f;
            float dd = degd > 0 ? rsqrtf((float)degd) : 0.f;
            swe[tid] = -ds * dd;
        }
        __syncthreads();
        if (tid < 16) {
            float ws = 0.f;
            if (tid < V)
                for (int e = 0; e < E; e++)
                    if (ei[E + e] == tid) ws += swe[e];
            sws[tid] = ws;
        }

        if (tid == 0) {
            while (atomicAdd(&g_ctr, 0) < NTASK) {
            }
        }
        __syncthreads();
        __threadfence();
        if (tid < 64) {
            cfo[tid] = chb[tid] + g_S[2 * br][tid];
            s1v[tid] = g_S[2 * br + 1][tid];
        }
        __syncthreads();

        const int lane = tid & 31, rp = tid >> 5;
        const int h = hc * 32 + lane;
        const int R = V * GO;
        const int RP = R >> 3;
        float acc = 0.f;
#pragma unroll 4
        for (int r = rp * RP; r < (rp + 1) * RP; r++) {
            int oo = r & 63, v = r >> 6;
            float coef = cfo[oo] + s1v[oo] * sws[v];
            acc += coef * P[r * H + h];
        }
        red2[tid] = acc;
        __syncthreads();
        if (tid < 32) {
            float s = pb[h];
#pragma unroll
            for (int j = 0; j < 8; j++) s += red2[j * 32 + lane];
            g_C[br][h] = s;
        }
    } else {
        const int NE = 256 * (KPE - KE);
        const int NR = 256 * (KPR - KR);
        __half z = __float2half_rn(0.f);
        for (int i = tid; i < NE + NR; i += 256) {
            size_t idx;
            if (i < NE) {
                int n = i / (KPE - KE), k = KE + i % (KPE - KE);
                idx = (size_t)n * KPE + k;
            } else {
                int r = i - NE;
                int n = r / (KPR - KR), k = KR + r % (KPR - KR);
                idx = (size_t)B_ERR_OFS + (size_t)n * KPR + k;
            }
            g_Bf[idx] = z;
        }
    }
}

// ===== GEMM: B-resident in registers, stream batch tiles =====
extern __shared__ char smg[];

template <int KP, int KREAL>
__device__ __forceinline__ void gemm_job(
    const float* __restrict__ X, const __half* __restrict__ Bsrc,
    float* __restrict__ G, int cg, int rb0, int tid, int wid, int lane) {
    constexpr int KS = KP / 16;
    constexpr int RS = KP * 2 + 16;
    char* sB = smg;
    char* sX = smg + 64 * RS;

    // ---- stage B slice once: 64 rows x KP halfs ----
    constexpr int UPT = (64 * KP * 2 / 16) / NTHR;
#pragma unroll
    for (int it = 0; it < UPT; it++) {
        int u = tid + it * NTHR;
        int n = u / (KP / 8);
        int q = u % (KP / 8);
        *(uint4*)(sB + n * RS + q * 16) =
            *(const uint4*)((const char*)Bsrc +
                            ((size_t)(cg * 64 + n) * KP + q * 8) * 2);
    }
    __syncthreads();

    // ---- hoist B fragments into registers (persistent) ----
    const int wm = wid & 1;          // m half (0/1)
    const int wn = wid >> 1;         // n group (0..7)
    const uint32_t suB = smem_u32(sB);
    const uint32_t suX = smem_u32(sX);
    const uint32_t brow =
        (uint32_t)((wn * 8 + (lane & 7)) * RS + (lane >> 3) * 16);
    uint32_t bfr[KS / 2][4];
#pragma unroll
    for (int h = 0; h < KS / 2; h++) ldsm4(bfr[h], suB + brow + h * 64);

    const uint32_t arow = (uint32_t)(
        (wm * 16 + (lane & 7) + (lane & 8)) * RS + (lane >> 4) * 16);
    const int g = lane >> 2, i2 = (lane & 3) * 2;
    constexpr int XPT = (32 * KP / 4) / NTHR;

    // ---- stream 8 batch tiles of 32 rows ----
#pragma unroll 1
    for (int t = 0; t < 8; t++) {
        __syncthreads();
        const int rbt = rb0 + t * 32;
#pragma unroll
        for (int it = 0; it < XPT; it++) {
            int u = tid + it * NTHR;
            int row = u / (KP / 4);
            int kq = u % (KP / 4);
            int k = kq * 4;
            float4 x = make_float4(0.f, 0.f, 0.f, 0.f);
            if (k < KREAL)
                x = *(const float4*)&X[(size_t)(rbt + row) * KREAL + k];
            *(uint2*)(sX + row * RS + kq * 8) = make_uint2(
                pack_h2(__float2half_rn(x.x), __float2half_rn(x.y)),
                pack_h2(__float2half_rn(x.z), __float2half_rn(x.w)));
        }
        __syncthreads();

        float d[4] = {0.f, 0.f, 0.f, 0.f};
#pragma unroll
        for (int ks = 0; ks < KS; ks++) {
            uint32_t aa[4];
            ldsm4(aa, suX + arow + ks * 32);
            mma16816(d, aa[0], aa[1], aa[2], aa[3],
                     bfr[ks >> 1][(ks & 1) * 2], bfr[ks >> 1][(ks & 1) * 2 + 1]);
        }
        const int row0 = rbt + wm * 16 + g;
        const int col = cg * 64 + wn * 8 + i2;
        *(float2*)&G[(size_t)row0 * H + col] = make_float2(d[0], d[1]);
        *(float2*)&G[(size_t)(row0 + 8) * H + col] = make_float2(d[2], d[3]);
    }
}

__global__ void __launch_bounds__(NTHR, 1)
k_gemm(const float* __restrict__ ecc, const float* __restrict__ err) {
    const int tid = threadIdx.x;
    const int wid = tid >> 5;
    const int lane = tid & 31;
    const int job = blockIdx.x & 7;
    const int rb0 = (blockIdx.x >> 3) * 256;
    const int br = job >> 2, cg = job & 3;

    if (blockIdx.x == 0 && tid == 0) g_ctr = 0;   // reset spin ctr (stream-ordered)

    if (br == 0)
        gemm_job<KPE, KE>(ecc, g_Bf, g_EG, cg, rb0, tid, wid, lane);
    else
        gemm_job<KPR, KR>(err, g_Bf + B_ERR_OFS, g_RG, cg, rb0, tid, wid, lane);
}

// ===== tail: gated fusion from global gates =====
__global__ void __launch_bounds__(256)
k_tail(const float* __restrict__ attnW, const float* __restrict__ attnb,
       const float* __restrict__ fc2W, const float* __restrict__ fc2b,
       float* __restrict__ out) {
    __shared__ float sC0[H], sC1[H], sAW[H], sFW[H];
    const int tid = threadIdx.x;
    const int wid = tid >> 5;    // 0..7
    const int lane = tid & 31;
    for (int i = tid; i < H; i += 256) {
        sC0[i] = g_C[0][i];
        sC1[i] = g_C[1][i];
        sAW[i] = attnW[i];
        sFW[i] = fc2W[i];
    }
    __syncthreads();

    const float attnb_v = attnb[0];
    const float fc2b_v = fc2b[0];
    const int r0 = blockIdx.x * 32 + wid * 4;
#pragma unroll
    for (int r = r0; r < r0 + 4; r++) {
        float ev[8], rv[8];
        float p = 0.f;
#pragma unroll
        for (int jj = 0; jj < 8; jj++) {
            int j = lane + jj * 32;
            ev[jj] = g_EG[(size_t)r * H + j] + sC0[j];
            rv[jj] = g_RG[(size_t)r * H + j] + sC1[j];
            p += tanhf(ev[jj] + rv[jj]) * sAW[j];
        }
#pragma unroll
        for (int o = 16; o; o >>= 1) p += __shfl_xor_sync(0xffffffffu, p, o);
        float attn = 1.f / (1.f + expf(-(p + attnb_v)));
        float q = 0.f;
#pragma unroll
        for (int jj = 0; jj < 8; jj++) {
            int j = lane + jj * 32;
            float f = attn * ev[jj] + (1.f - attn) * rv[jj];
            q += fmaxf(f, 0.f) * sFW[j];
        }
#pragma unroll
        for (int o = 16; o; o >>= 1) q += __shfl_xor_sync(0xffffffffu, q, o);
        if (lane == 0) out[r] = 1.f / (1.f + expf(-(q + fc2b_v)));
    }
}

// ---------------- launch ----------------
extern "C" void kernel_launch(void* const* d_in, const int* in_sizes, int n_in,
                              void* d_out, int out_size) {
    const float* ecc = (const float*)d_in[0];
    const float* err = (const float*)d_in[1];
    const float* conv_ecc_w = (const float*)d_in[2];
    const float* conv_ecc_b = (const float*)d_in[3];
    const float* conv_err_w = (const float*)d_in[4];
    const float* conv_err_b = (const float*)d_in[5];
    const float* cheb_ecc_W = (const float*)d_in[6];
    const float* cheb_ecc_b = (const float*)d_in[7];
    const float* cheb_err_W = (const float*)d_in[8];
    const float* cheb_err_b = (const float*)d_in[9];
    const float* ecc_proj_W = (const float*)d_in[10];
    const float* ecc_proj_b = (const float*)d_in[11];
    const float* err_proj_W = (const float*)d_in[12];
    const float* err_proj_b = (const float*)d_in[13];
    const float* attn_W = (const float*)d_in[14];
    const float* attn_b = (const float*)d_in[15];
    const float* fc2_W = (const float*)d_in[16];
    const float* fc2_b = (const float*)d_in[17];
    const int* ei_ecc = (const int*)d_in[18];
    const int* ei_err = (const int*)d_in[19];
    const int Ee = in_sizes[18] / 2;
    const int Er = in_sizes[19] / 2;

    k_pre2<<<(VE + VR) * 4 + 17, 256>>>(
        ecc_proj_W, err_proj_W, ecc_proj_b, err_proj_b,
        cheb_ecc_b, cheb_err_b,
        conv_ecc_w, conv_ecc_b, conv_err_w, conv_err_b,
        cheb_ecc_W, cheb_err_W, ei_ecc, Ee, ei_err, Er);

    cudaFuncSetAttribute(k_gemm, cudaFuncAttributeMaxDynamicSharedMemorySize,
                         SM_GEMM);
    k_gemm<<<128, NTHR, SM_GEMM>>>(ecc, err);

    k_tail<<<BATCH / 32, 256>>>(attn_W, attn_b, fc2_W, fc2_b, (float*)d_out);
}